// round 12
// baseline (speedup 1.0000x reference)
#include <cuda_runtime.h>
#include <math.h>

#define TPB 96          // 3 warps: warp0=Y, warp1/2=chroma; 1 thread = one 8x8 block
#define RMAGIC 12582912.0f   // 1.5*2^23: (x+M)-M = round-half-even(x) for |x|<2^22

// 1-D orthonormal DCT-II coefficients: Kn = 0.5*cos(n*pi/16), K4 includes 1/sqrt(2)
#define K1 0.49039264020161522f
#define K2 0.46193976625564337f
#define K3 0.41573480615127262f
#define K4 0.35355339059327376f
#define K5 0.27778511650980111f
#define K6 0.19134171618254489f
#define K7 0.097545161008064134f

// JPEG quant tables (constants of the reference)
static __device__ constexpr float QLUM[64] = {
    16,11,10,16,24,40,51,61,  12,12,14,19,26,58,60,55,
    14,13,16,24,40,57,69,56,  14,17,22,29,51,87,80,62,
    18,22,37,56,68,109,103,77, 24,35,55,64,81,104,113,92,
    49,64,78,87,103,121,120,101, 72,92,95,98,112,100,103,99};
static __device__ constexpr float QCHR[64] = {
    17,18,24,47,99,99,99,99,  18,21,26,66,99,99,99,99,
    24,26,56,99,99,99,99,99,  47,66,99,99,99,99,99,99,
    99,99,99,99,99,99,99,99,  99,99,99,99,99,99,99,99,
    99,99,99,99,99,99,99,99,  99,99,99,99,99,99,99,99};

// 8-point DCT (stride S): even half via butterflies (12 ops), odd half 4 chains (16 ops).
// Same matrix applies for the reference's "inverse" (it re-contracts with M).
template<int S>
__device__ __forceinline__ void dct8(float* __restrict__ x)
{
    float s0 = x[0*S] + x[7*S], s1 = x[1*S] + x[6*S];
    float s2 = x[2*S] + x[5*S], s3 = x[3*S] + x[4*S];
    float d0 = x[0*S] - x[7*S], d1 = x[1*S] - x[6*S];
    float d2 = x[2*S] - x[5*S], d3 = x[3*S] - x[4*S];
    float e0 = s0 + s3, e1 = s1 + s2;
    float e2 = s0 - s3, e3 = s1 - s2;
    x[0*S] = K4 * (e0 + e1);
    x[4*S] = K4 * (e0 - e1);
    x[2*S] = fmaf( K6, e3, K2 * e2);
    x[6*S] = fmaf(-K2, e3, K6 * e2);
    x[1*S] = fmaf( K7, d3, fmaf( K5, d2, fmaf( K3, d1, K1 * d0)));
    x[3*S] = fmaf(-K5, d3, fmaf(-K1, d2, fmaf(-K7, d1, K3 * d0)));
    x[5*S] = fmaf( K3, d3, fmaf( K7, d2, fmaf(-K1, d1, K5 * d0)));
    x[7*S] = fmaf(-K1, d3, fmaf( K3, d2, fmaf(-K5, d1, K7 * d0)));
}

// quant/dequant via magic-constant round-half-even: all fast-pipe imm ops, no FRND
__device__ __forceinline__ void quant64(float* __restrict__ B, const float* __restrict__ Q)
{
    #pragma unroll
    for (int j = 0; j < 64; j++) {
        float t = fmaf(B[j], 1.0f / Q[j], RMAGIC);   // 1/Q folds to an immediate
        B[j] = (t - RMAGIC) * Q[j];
    }
}

// smem layout: block b (0..95) occupies words [b*64, b*64+64); float4 slot s of
// block b lives at word b*64 + 4*(s ^ (b&7)).  Every 8-lane LDS/STS.128 phase in
// phases 1,2,3 then covers all 8 bank-quads: conflict-free, zero padding.
__global__ __launch_bounds__(TPB, 7)          // 96 regs -> 7 CTAs = 21 warps/SM
void jpeg_kernel(const float* __restrict__ img, float* __restrict__ out)
{
    __shared__ float sB[TPB * 64];            // 24 KB

    const int tid = threadIdx.x;
    const int gx0 = blockIdx.x << 6;    // 64-wide region
    const int gy0 = blockIdx.y << 5;    // 32-tall region
    const size_t plane = 512 * 512;
    const float* src = img + (size_t)blockIdx.z * 3 * plane;
    float*       dst = out + (size_t)blockIdx.z * 3 * plane;

    // ---- phase 1: load RGB (float4), RGB->YUV, *255-128, swizzled block-major scatter ----
    #pragma unroll
    for (int it = 0; it < 6; it++) {
        int v = tid + it * TPB;
        if (v < 512) {                       // 512 float4 groups in a 32x64 region
            int bx = v & 7;                  // 8-col block within row strip
            int hf = (v >> 3) & 1;           // which float4 half of the 8 cols
            int ly = v >> 4;                 // 0..31
            int lx = (bx << 3) + (hf << 2);
            size_t poff = (size_t)(gy0 + ly) * 512 + (gx0 + lx);
            float4 R4 = *(const float4*)(src + poff);
            float4 G4 = *(const float4*)(src + plane + poff);
            float4 B4 = *(const float4*)(src + 2 * plane + poff);
            int s = ((ly & 7) << 1) + hf;                 // slot 0..15
            int w = (s ^ bx) << 2;                        // swizzled word in block
            int b0 = (((ly >> 3) << 3) + bx) << 6;        // Y block base (blocks 0..31)
            float rr[4] = {R4.x, R4.y, R4.z, R4.w};
            float gg[4] = {G4.x, G4.y, G4.z, G4.w};
            float bb[4] = {B4.x, B4.y, B4.z, B4.w};
            float yv[4], uv[4], vv[4];
            #pragma unroll
            for (int j = 0; j < 4; j++) {
                float Y = fmaf(0.114f,  bb[j], fmaf(0.587f,   gg[j], 0.299f   * rr[j]));
                float U = fmaf(0.5f,    bb[j], fmaf(-0.3313f, gg[j], -0.1687f * rr[j]));
                float V = fmaf(-0.0813f,bb[j], fmaf(-0.4187f, gg[j], 0.5f     * rr[j]));
                yv[j] = fmaf(Y, 255.0f, -128.0f);
                uv[j] = fmaf(U, 255.0f, -128.0f);
                vv[j] = fmaf(V, 255.0f, -128.0f);
            }
            *(float4*)&sB[b0 + w]             = make_float4(yv[0], yv[1], yv[2], yv[3]);
            *(float4*)&sB[b0 + 32 * 64 + w]   = make_float4(uv[0], uv[1], uv[2], uv[3]);
            *(float4*)&sB[b0 + 64 * 64 + w]   = make_float4(vv[0], vv[1], vv[2], vv[3]);
        }
    }

    __syncthreads();

    // ---- phase 2: per-thread 8x8, scalar immediates, all in registers ----
    {
        const int swl = tid & 7;
        float* myB = &sB[tid << 6];
        float B[64];
        #pragma unroll
        for (int r = 0; r < 8; r++)
            #pragma unroll
            for (int h = 0; h < 2; h++) {
                float4 t = *(const float4*)&myB[((2 * r + h) ^ swl) << 2];
                int o = r * 8 + h * 4;
                B[o] = t.x;  B[o+1] = t.y;  B[o+2] = t.z;  B[o+3] = t.w;
            }

        #pragma unroll
        for (int r = 0; r < 8; r++) dct8<1>(&B[r * 8]);   // rows (contract over y -> v)
        #pragma unroll
        for (int c = 0; c < 8; c++) dct8<8>(&B[c]);       // cols (contract over x -> u)

        if (tid < 32) quant64(B, QLUM);       // warp-uniform branch: warp0 = Y
        else          quant64(B, QCHR);       // warps 1,2 = chroma

        #pragma unroll
        for (int c = 0; c < 8; c++) dct8<8>(&B[c]);       // reference "inverse" reuses M
        #pragma unroll
        for (int r = 0; r < 8; r++) dct8<1>(&B[r * 8]);

        #pragma unroll
        for (int r = 0; r < 8; r++)
            #pragma unroll
            for (int h = 0; h < 2; h++) {
                int o = r * 8 + h * 4;
                *(float4*)&myB[((2 * r + h) ^ swl) << 2] =
                    make_float4(B[o], B[o+1], B[o+2], B[o+3]);
            }
    }

    __syncthreads();

    // ---- phase 3: +128, /255, YUV->RGB, float4 stores ----
    const float inv255 = 1.0f / 255.0f;
    #pragma unroll
    for (int it = 0; it < 6; it++) {
        int v = tid + it * TPB;
        if (v < 512) {
            int bx = v & 7;
            int hf = (v >> 3) & 1;
            int ly = v >> 4;
            int lx = (bx << 3) + (hf << 2);
            size_t poff = (size_t)(gy0 + ly) * 512 + (gx0 + lx);
            int s = ((ly & 7) << 1) + hf;
            int w = (s ^ bx) << 2;
            int b0 = (((ly >> 3) << 3) + bx) << 6;
            float4 y4 = *(const float4*)&sB[b0 + w];
            float4 u4 = *(const float4*)&sB[b0 + 32 * 64 + w];
            float4 v4 = *(const float4*)&sB[b0 + 64 * 64 + w];
            float yy[4] = {y4.x, y4.y, y4.z, y4.w};
            float uu[4] = {u4.x, u4.y, u4.z, u4.w};
            float vv[4] = {v4.x, v4.y, v4.z, v4.w};
            float ro[4], go[4], bo[4];
            #pragma unroll
            for (int j = 0; j < 4; j++) {
                float Y = (yy[j] + 128.0f) * inv255;
                float U = (uu[j] + 128.0f) * inv255;
                float V = (vv[j] + 128.0f) * inv255;
                ro[j] = fmaf(1.402f, V, Y);
                go[j] = fmaf(-0.71414f, V, fmaf(-0.34414f, U, Y));
                bo[j] = fmaf(1.772f, U, Y);
            }
            *(float4*)(dst + poff)             = make_float4(ro[0], ro[1], ro[2], ro[3]);
            *(float4*)(dst + plane + poff)     = make_float4(go[0], go[1], go[2], go[3]);
            *(float4*)(dst + 2 * plane + poff) = make_float4(bo[0], bo[1], bo[2], bo[3]);
        }
    }
}

extern "C" void kernel_launch(void* const* d_in, const int* in_sizes, int n_in,
                              void* d_out, int out_size)
{
    const float* img = (const float*)d_in[0];
    int nbatch = in_sizes[0] / (3 * 512 * 512);   // 16 for this problem
    dim3 grid(512 / 64, 512 / 32, nbatch);
    jpeg_kernel<<<grid, TPB>>>(img, (float*)d_out);
}

// round 13
// speedup vs baseline: 1.0012x; 1.0012x over previous
#include <cuda_runtime.h>
#include <math.h>

#define TPB 96          // 3 warps: warp0=Y, warp1/2=chroma; 1 thread = one 8x8 block
#define BSTRIDE 68      // multiple of 4: LDS.128/STS.128 conflict-free in phase 2
#define RMAGIC 12582912.0f   // 1.5*2^23: (x+M)-M = round-half-even(x) for |x|<2^22

// 1-D orthonormal DCT-II coefficients: Kn = 0.5*cos(n*pi/16), K4 includes 1/sqrt(2)
#define K1 0.49039264020161522f
#define K2 0.46193976625564337f
#define K3 0.41573480615127262f
#define K4 0.35355339059327376f
#define K5 0.27778511650980111f
#define K6 0.19134171618254489f
#define K7 0.097545161008064134f

// JPEG quant tables (constants of the reference)
static __device__ constexpr float QLUM[64] = {
    16,11,10,16,24,40,51,61,  12,12,14,19,26,58,60,55,
    14,13,16,24,40,57,69,56,  14,17,22,29,51,87,80,62,
    18,22,37,56,68,109,103,77, 24,35,55,64,81,104,113,92,
    49,64,78,87,103,121,120,101, 72,92,95,98,112,100,103,99};
static __device__ constexpr float QCHR[64] = {
    17,18,24,47,99,99,99,99,  18,21,26,66,99,99,99,99,
    24,26,56,99,99,99,99,99,  47,66,99,99,99,99,99,99,
    99,99,99,99,99,99,99,99,  99,99,99,99,99,99,99,99,
    99,99,99,99,99,99,99,99,  99,99,99,99,99,99,99,99};

// 8-point DCT (stride S): even half via butterflies (12 ops), odd half 4 chains (16 ops).
// Same matrix applies for the reference's "inverse" (it re-contracts with M).
template<int S>
__device__ __forceinline__ void dct8(float* __restrict__ x)
{
    float s0 = x[0*S] + x[7*S], s1 = x[1*S] + x[6*S];
    float s2 = x[2*S] + x[5*S], s3 = x[3*S] + x[4*S];
    float d0 = x[0*S] - x[7*S], d1 = x[1*S] - x[6*S];
    float d2 = x[2*S] - x[5*S], d3 = x[3*S] - x[4*S];
    float e0 = s0 + s3, e1 = s1 + s2;
    float e2 = s0 - s3, e3 = s1 - s2;
    x[0*S] = K4 * (e0 + e1);
    x[4*S] = K4 * (e0 - e1);
    x[2*S] = fmaf( K6, e3, K2 * e2);
    x[6*S] = fmaf(-K2, e3, K6 * e2);
    x[1*S] = fmaf( K7, d3, fmaf( K5, d2, fmaf( K3, d1, K1 * d0)));
    x[3*S] = fmaf(-K5, d3, fmaf(-K1, d2, fmaf(-K7, d1, K3 * d0)));
    x[5*S] = fmaf( K3, d3, fmaf( K7, d2, fmaf(-K1, d1, K5 * d0)));
    x[7*S] = fmaf(-K1, d3, fmaf( K3, d2, fmaf(-K5, d1, K7 * d0)));
}

// quant/dequant via magic-constant round-half-even: all fast-pipe imm ops, no FRND
__device__ __forceinline__ void quant64(float* __restrict__ B, const float* __restrict__ Q)
{
    #pragma unroll
    for (int j = 0; j < 64; j++) {
        float t = fmaf(B[j], 1.0f / Q[j], RMAGIC);   // 1/Q folds to an immediate
        B[j] = (t - RMAGIC) * Q[j];
    }
}

__global__ __launch_bounds__(TPB, 7)          // 96 regs * 96 thr * 7 = 64512 <= 64K
void jpeg_kernel(const float* __restrict__ img, float* __restrict__ out)
{
    __shared__ float sB[TPB * BSTRIDE];

    const int tid = threadIdx.x;
    const int gx0 = blockIdx.x << 6;    // 64-wide region
    const int gy0 = blockIdx.y << 5;    // 32-tall region
    const size_t plane = 512 * 512;
    const float* src = img + (size_t)blockIdx.z * 3 * plane;
    float*       dst = out + (size_t)blockIdx.z * 3 * plane;

    // ---- phase 1: load RGB (float4), RGB->YUV, *255-128, block-major scatter ----
    // lane map bx=v&7, hf=(v>>3)&1: 8 consecutive lanes hit 8 DISTINCT blocks ->
    // bank-quad (17*(b+k)+s) mod 8 distinct over k: STS.128 conflict-free, no swizzle.
    #pragma unroll
    for (int it = 0; it < 6; it++) {
        int v = tid + it * TPB;
        if (v < 512) {                       // 512 float4 groups in a 32x64 region
            int bx = v & 7;                  // 8-col block within row strip
            int hf = (v >> 3) & 1;           // which float4 half of the 8 cols
            int ly = v >> 4;                 // 0..31
            int lx = (bx << 3) + (hf << 2);
            size_t poff = (size_t)(gy0 + ly) * 512 + (gx0 + lx);
            float4 R4 = *(const float4*)(src + poff);
            float4 G4 = *(const float4*)(src + plane + poff);
            float4 B4 = *(const float4*)(src + 2 * plane + poff);
            int base = (((ly >> 3) << 3) + bx) * BSTRIDE + ((ly & 7) << 3) + (hf << 2);
            float rr[4] = {R4.x, R4.y, R4.z, R4.w};
            float gg[4] = {G4.x, G4.y, G4.z, G4.w};
            float bb[4] = {B4.x, B4.y, B4.z, B4.w};
            float yv[4], uv[4], vv[4];
            #pragma unroll
            for (int j = 0; j < 4; j++) {
                float Y = fmaf(0.114f,  bb[j], fmaf(0.587f,   gg[j], 0.299f   * rr[j]));
                float U = fmaf(0.5f,    bb[j], fmaf(-0.3313f, gg[j], -0.1687f * rr[j]));
                float V = fmaf(-0.0813f,bb[j], fmaf(-0.4187f, gg[j], 0.5f     * rr[j]));
                yv[j] = fmaf(Y, 255.0f, -128.0f);
                uv[j] = fmaf(U, 255.0f, -128.0f);
                vv[j] = fmaf(V, 255.0f, -128.0f);
            }
            *(float4*)&sB[base]                = make_float4(yv[0], yv[1], yv[2], yv[3]);
            *(float4*)&sB[base + 32 * BSTRIDE] = make_float4(uv[0], uv[1], uv[2], uv[3]);
            *(float4*)&sB[base + 64 * BSTRIDE] = make_float4(vv[0], vv[1], vv[2], vv[3]);
        }
    }

    __syncthreads();

    // ---- phase 2: per-thread 8x8, scalar immediates, static smem offsets ----
    {
        float* myB = &sB[tid * BSTRIDE];
        float B[64];
        #pragma unroll
        for (int i = 0; i < 16; i++) {       // LDS.128, conflict-free (stride 68)
            float4 t = *(const float4*)(&myB[4 * i]);
            B[4*i] = t.x;  B[4*i+1] = t.y;  B[4*i+2] = t.z;  B[4*i+3] = t.w;
        }

        #pragma unroll
        for (int r = 0; r < 8; r++) dct8<1>(&B[r * 8]);   // rows (contract over y -> v)
        #pragma unroll
        for (int c = 0; c < 8; c++) dct8<8>(&B[c]);       // cols (contract over x -> u)

        if (tid < 32) quant64(B, QLUM);       // warp-uniform branch: warp0 = Y
        else          quant64(B, QCHR);       // warps 1,2 = chroma

        #pragma unroll
        for (int c = 0; c < 8; c++) dct8<8>(&B[c]);       // reference "inverse" reuses M
        #pragma unroll
        for (int r = 0; r < 8; r++) dct8<1>(&B[r * 8]);

        #pragma unroll
        for (int i = 0; i < 16; i++)
            *(float4*)(&myB[4 * i]) = make_float4(B[4*i], B[4*i+1], B[4*i+2], B[4*i+3]);
    }

    __syncthreads();

    // ---- phase 3: +128, /255, YUV->RGB, float4 stores ----
    const float inv255 = 1.0f / 255.0f;
    #pragma unroll
    for (int it = 0; it < 6; it++) {
        int v = tid + it * TPB;
        if (v < 512) {
            int bx = v & 7;
            int hf = (v >> 3) & 1;
            int ly = v >> 4;
            int lx = (bx << 3) + (hf << 2);
            size_t poff = (size_t)(gy0 + ly) * 512 + (gx0 + lx);
            int base = (((ly >> 3) << 3) + bx) * BSTRIDE + ((ly & 7) << 3) + (hf << 2);
            float4 y4 = *(const float4*)&sB[base];
            float4 u4 = *(const float4*)&sB[base + 32 * BSTRIDE];
            float4 v4 = *(const float4*)&sB[base + 64 * BSTRIDE];
            float yy[4] = {y4.x, y4.y, y4.z, y4.w};
            float uu[4] = {u4.x, u4.y, u4.z, u4.w};
            float vv[4] = {v4.x, v4.y, v4.z, v4.w};
            float ro[4], go[4], bo[4];
            #pragma unroll
            for (int j = 0; j < 4; j++) {
                float Y = (yy[j] + 128.0f) * inv255;
                float U = (uu[j] + 128.0f) * inv255;
                float V = (vv[j] + 128.0f) * inv255;
                ro[j] = fmaf(1.402f, V, Y);
                go[j] = fmaf(-0.71414f, V, fmaf(-0.34414f, U, Y));
                bo[j] = fmaf(1.772f, U, Y);
            }
            *(float4*)(dst + poff)             = make_float4(ro[0], ro[1], ro[2], ro[3]);
            *(float4*)(dst + plane + poff)     = make_float4(go[0], go[1], go[2], go[3]);
            *(float4*)(dst + 2 * plane + poff) = make_float4(bo[0], bo[1], bo[2], bo[3]);
        }
    }
}

extern "C" void kernel_launch(void* const* d_in, const int* in_sizes, int n_in,
                              void* d_out, int out_size)
{
    const float* img = (const float*)d_in[0];
    int nbatch = in_sizes[0] / (3 * 512 * 512);   // 16 for this problem
    dim3 grid(512 / 64, 512 / 32, nbatch);
    jpeg_kernel<<<grid, TPB>>>(img, (float*)d_out);
}

// round 17
// speedup vs baseline: 1.0804x; 1.0791x over previous
#include <cuda_runtime.h>
#include <math.h>

#define TPB 96          // 3 warps: warp0=Y, warp1/2=chroma; 1 thread = one 8x8 block
#define BSTRIDE 68      // multiple of 4: LDS.128/STS.128 conflict-free in phase 2
#define RMAGIC 12582912.0f   // 1.5*2^23: (x+M)-M = round-half-even(x) for |x|<2^22

// 1-D orthonormal DCT-II coefficients: Kn = 0.5*cos(n*pi/16), K4 includes 1/sqrt(2)
#define K1 0.49039264020161522f
#define K2 0.46193976625564337f
#define K3 0.41573480615127262f
#define K4 0.35355339059327376f
#define K5 0.27778511650980111f
#define K6 0.19134171618254489f
#define K7 0.097545161008064134f

// JPEG quant tables (constants of the reference)
static __device__ constexpr float QLUM[64] = {
    16,11,10,16,24,40,51,61,  12,12,14,19,26,58,60,55,
    14,13,16,24,40,57,69,56,  14,17,22,29,51,87,80,62,
    18,22,37,56,68,109,103,77, 24,35,55,64,81,104,113,92,
    49,64,78,87,103,121,120,101, 72,92,95,98,112,100,103,99};
static __device__ constexpr float QCHR[64] = {
    17,18,24,47,99,99,99,99,  18,21,26,66,99,99,99,99,
    24,26,56,99,99,99,99,99,  47,66,99,99,99,99,99,99,
    99,99,99,99,99,99,99,99,  99,99,99,99,99,99,99,99,
    99,99,99,99,99,99,99,99,  99,99,99,99,99,99,99,99};

// 8-point DCT (stride S): even half via butterflies (12 ops), odd half 4 chains (16 ops).
// Same matrix applies for the reference's "inverse" (it re-contracts with M).
template<int S>
__device__ __forceinline__ void dct8(float* __restrict__ x)
{
    float s0 = x[0*S] + x[7*S], s1 = x[1*S] + x[6*S];
    float s2 = x[2*S] + x[5*S], s3 = x[3*S] + x[4*S];
    float d0 = x[0*S] - x[7*S], d1 = x[1*S] - x[6*S];
    float d2 = x[2*S] - x[5*S], d3 = x[3*S] - x[4*S];
    float e0 = s0 + s3, e1 = s1 + s2;
    float e2 = s0 - s3, e3 = s1 - s2;
    x[0*S] = K4 * (e0 + e1);
    x[4*S] = K4 * (e0 - e1);
    x[2*S] = fmaf( K6, e3, K2 * e2);
    x[6*S] = fmaf(-K2, e3, K6 * e2);
    x[1*S] = fmaf( K7, d3, fmaf( K5, d2, fmaf( K3, d1, K1 * d0)));
    x[3*S] = fmaf(-K5, d3, fmaf(-K1, d2, fmaf(-K7, d1, K3 * d0)));
    x[5*S] = fmaf( K3, d3, fmaf( K7, d2, fmaf(-K1, d1, K5 * d0)));
    x[7*S] = fmaf(-K1, d3, fmaf( K3, d2, fmaf(-K5, d1, K7 * d0)));
}

// quant/dequant via magic-constant round-half-even: all fast-pipe imm ops, no FRND
__device__ __forceinline__ void quant64(float* __restrict__ B, const float* __restrict__ Q)
{
    #pragma unroll
    for (int j = 0; j < 64; j++) {
        float t = fmaf(B[j], 1.0f / Q[j], RMAGIC);   // 1/Q folds to an immediate
        B[j] = (t - RMAGIC) * Q[j];
    }
}

__global__ __launch_bounds__(TPB, 6)          // reg target 112: keep the 96-reg ILP machine
void jpeg_kernel(const float* __restrict__ img, float* __restrict__ out)
{
    __shared__ float sB[TPB * BSTRIDE];

    const int tid = threadIdx.x;
    const int gx0 = blockIdx.x << 6;    // 64-wide region
    const int gy0 = blockIdx.y << 5;    // 32-tall region
    const size_t plane = 512 * 512;
    const float* src = img + (size_t)blockIdx.z * 3 * plane;
    float*       dst = out + (size_t)blockIdx.z * 3 * plane;

    // ---- phase 1: load RGB (float4), RGB->YUV, *255-128, block-major scatter ----
    // lane map bx=v&7, hf=(v>>3)&1: 8 consecutive lanes hit 8 DISTINCT blocks ->
    // bank-quad (17*(b+k)+s) mod 8 distinct over k: STS.128 conflict-free, no swizzle.
    #pragma unroll
    for (int it = 0; it < 6; it++) {
        int v = tid + it * TPB;
        if (v < 512) {                       // 512 float4 groups in a 32x64 region
            int bx = v & 7;                  // 8-col block within row strip
            int hf = (v >> 3) & 1;           // which float4 half of the 8 cols
            int ly = v >> 4;                 // 0..31
            int lx = (bx << 3) + (hf << 2);
            size_t poff = (size_t)(gy0 + ly) * 512 + (gx0 + lx);
            float4 R4 = *(const float4*)(src + poff);
            float4 G4 = *(const float4*)(src + plane + poff);
            float4 B4 = *(const float4*)(src + 2 * plane + poff);
            int base = (((ly >> 3) << 3) + bx) * BSTRIDE + ((ly & 7) << 3) + (hf << 2);
            float rr[4] = {R4.x, R4.y, R4.z, R4.w};
            float gg[4] = {G4.x, G4.y, G4.z, G4.w};
            float bb[4] = {B4.x, B4.y, B4.z, B4.w};
            float yv[4], uv[4], vv[4];
            #pragma unroll
            for (int j = 0; j < 4; j++) {
                float Y = fmaf(0.114f,  bb[j], fmaf(0.587f,   gg[j], 0.299f   * rr[j]));
                float U = fmaf(0.5f,    bb[j], fmaf(-0.3313f, gg[j], -0.1687f * rr[j]));
                float V = fmaf(-0.0813f,bb[j], fmaf(-0.4187f, gg[j], 0.5f     * rr[j]));
                yv[j] = fmaf(Y, 255.0f, -128.0f);
                uv[j] = fmaf(U, 255.0f, -128.0f);
                vv[j] = fmaf(V, 255.0f, -128.0f);
            }
            *(float4*)&sB[base]                = make_float4(yv[0], yv[1], yv[2], yv[3]);
            *(float4*)&sB[base + 32 * BSTRIDE] = make_float4(uv[0], uv[1], uv[2], uv[3]);
            *(float4*)&sB[base + 64 * BSTRIDE] = make_float4(vv[0], vv[1], vv[2], vv[3]);
        }
    }

    __syncthreads();

    // ---- phase 2: per-thread 8x8, scalar immediates, static smem offsets ----
    {
        float* myB = &sB[tid * BSTRIDE];
        float B[64];
        #pragma unroll
        for (int i = 0; i < 16; i++) {       // LDS.128, conflict-free (stride 68)
            float4 t = *(const float4*)(&myB[4 * i]);
            B[4*i] = t.x;  B[4*i+1] = t.y;  B[4*i+2] = t.z;  B[4*i+3] = t.w;
        }

        #pragma unroll
        for (int r = 0; r < 8; r++) dct8<1>(&B[r * 8]);   // rows (contract over y -> v)
        #pragma unroll
        for (int c = 0; c < 8; c++) dct8<8>(&B[c]);       // cols (contract over x -> u)

        if (tid < 32) quant64(B, QLUM);       // warp-uniform branch: warp0 = Y
        else          quant64(B, QCHR);       // warps 1,2 = chroma

        #pragma unroll
        for (int c = 0; c < 8; c++) dct8<8>(&B[c]);       // reference "inverse" reuses M
        #pragma unroll
        for (int r = 0; r < 8; r++) dct8<1>(&B[r * 8]);

        #pragma unroll
        for (int i = 0; i < 16; i++)
            *(float4*)(&myB[4 * i]) = make_float4(B[4*i], B[4*i+1], B[4*i+2], B[4*i+3]);
    }

    __syncthreads();

    // ---- phase 3: +128, /255, YUV->RGB, float4 stores ----
    const float inv255 = 1.0f / 255.0f;
    #pragma unroll
    for (int it = 0; it < 6; it++) {
        int v = tid + it * TPB;
        if (v < 512) {
            int bx = v & 7;
            int hf = (v >> 3) & 1;
            int ly = v >> 4;
            int lx = (bx << 3) + (hf << 2);
            size_t poff = (size_t)(gy0 + ly) * 512 + (gx0 + lx);
            int base = (((ly >> 3) << 3) + bx) * BSTRIDE + ((ly & 7) << 3) + (hf << 2);
            float4 y4 = *(const float4*)&sB[base];
            float4 u4 = *(const float4*)&sB[base + 32 * BSTRIDE];
            float4 v4 = *(const float4*)&sB[base + 64 * BSTRIDE];
            float yy[4] = {y4.x, y4.y, y4.z, y4.w};
            float uu[4] = {u4.x, u4.y, u4.z, u4.w};
            float vv[4] = {v4.x, v4.y, v4.z, v4.w};
            float ro[4], go[4], bo[4];
            #pragma unroll
            for (int j = 0; j < 4; j++) {
                float Y = (yy[j] + 128.0f) * inv255;
                float U = (uu[j] + 128.0f) * inv255;
                float V = (vv[j] + 128.0f) * inv255;
                ro[j] = fmaf(1.402f, V, Y);
                go[j] = fmaf(-0.71414f, V, fmaf(-0.34414f, U, Y));
                bo[j] = fmaf(1.772f, U, Y);
            }
            *(float4*)(dst + poff)             = make_float4(ro[0], ro[1], ro[2], ro[3]);
            *(float4*)(dst + plane + poff)     = make_float4(go[0], go[1], go[2], go[3]);
            *(float4*)(dst + 2 * plane + poff) = make_float4(bo[0], bo[1], bo[2], bo[3]);
        }
    }
}

extern "C" void kernel_launch(void* const* d_in, const int* in_sizes, int n_in,
                              void* d_out, int out_size)
{
    const float* img = (const float*)d_in[0];
    int nbatch = in_sizes[0] / (3 * 512 * 512);   // 16 for this problem
    dim3 grid(512 / 64, 512 / 32, nbatch);
    jpeg_kernel<<<grid, TPB>>>(img, (float*)d_out);
}